// round 14
// baseline (speedup 1.0000x reference)
#include <cuda_runtime.h>
#include <cstdint>
#include <math.h>

// ---------------------------------------------------------------------------
// NeuralODE Tsit5 — persistent-CTA fp32 kernel, round 11.
// = the proven 22.8ms kernel (512thr/TM=32) rescaled to TM=16, 256 threads,
//   NCTA=256, __launch_bounds__(256,2): TWO independent CTAs per SM so that
//   barrier/latency stalls of one CTA are covered by the other's warps.
// Per-SM FMA and L1 demand identical to the 22.8ms config.
// ---------------------------------------------------------------------------

#define BATCH   4096
#define DIM     64
#define WIDTH   256
#define NTT     101
#define TM      16
#define NCTA    (BATCH / TM)      // 256
#define THREADS 256

// row swizzle: element r (0..15) of feature-row n at slot r ^ SWR(n)
#define SWR(idx) ((((idx) >> 3) & 3) << 2)   // {0,4,8,12}, constant per 8-k group

#define ACT_SIZE (WIDTH * TM)     // 4096 floats (16KB)
#define ZK_SIZE  (DIM * TM)       // 1024 floats (4KB)
#define RED_SIZE (WIDTH * TM)     // 4096 floats

#define SMEM_FLOATS (2*ACT_SIZE + 2*RED_SIZE + ZK_SIZE + ZK_SIZE + 6*ZK_SIZE)
#define SMEM_BYTES  (SMEM_FLOATS * 4)   // 96KB per CTA -> 2 CTAs/SM

// Tsit5 tableau
__constant__ float c_A[6][5] = {
    {0.f, 0.f, 0.f, 0.f, 0.f},
    {0.161f, 0.f, 0.f, 0.f, 0.f},
    {-0.008480655492356989f, 0.335480655492357f, 0.f, 0.f, 0.f},
    {2.8971530571054935f, -6.359448489975075f, 4.3622954328695815f, 0.f, 0.f},
    {5.325864828439257f, -11.748883564062828f, 7.4955393428898365f, -0.09249506636175525f, 0.f},
    {5.86145544294642f, -12.92096931784711f, 8.159367898576159f, -0.071584973281401f, -0.028269050394068383f}
};
__constant__ float c_B[6] = {
    0.09646076681806523f, 0.01f, 0.4798896504144996f,
    1.379008574103742f, -3.290069515436081f, 2.324710524099774f
};

// ---- packed f32x2 helpers ----
__device__ __forceinline__ unsigned long long pk2(float lo, float hi) {
    unsigned long long r;
    asm("mov.b64 %0, {%1, %2};" : "=l"(r) : "f"(lo), "f"(hi));
    return r;
}
__device__ __forceinline__ void upk2(unsigned long long v, float &lo, float &hi) {
    asm("mov.b64 {%0, %1}, %2;" : "=f"(lo), "=f"(hi) : "l"(v));
}
__device__ __forceinline__ void ffma2(unsigned long long &d,
                                      unsigned long long a,
                                      unsigned long long b) {
    asm("fma.rn.f32x2 %0, %1, %2, %0;" : "+l"(d) : "l"(a), "l"(b));
}

// ---------------------------------------------------------------------------
// Dense layer, split-K=4, thread tile 8 rows x CPL cols (R5 geometry):
//   Aout[c][r^SWR(c)] = act( sum_k W[k][c] * Ain[k][r^SWR(k)] + b[c] )
// Warp w (8 warps): ks = w>>1 (k-slice 0..3), rg = w&1 (rows rg*8..+7).
// Lane: CPL = N/32 columns at lane*CPL. W via LDG (L2-resident), 1-deep
// prefetch. 3-phase SMEM split-K reduction.
// ---------------------------------------------------------------------------
template <int K, int N, bool ACT>
__device__ __forceinline__ void layerT(const float *Ain, float *Aout,
                                       const float *__restrict__ Wg,
                                       const float *__restrict__ bg,
                                       float *red0, float *red1) {
    constexpr int CPL  = N / 32;       // 8 (N=256) or 2 (N=64)
    constexpr int KS   = K / 4;        // 64 or 16
    constexpr int NGRP = KS / 8;       // 8 or 2

    const int tid  = threadIdx.x;
    const int w    = tid >> 5;
    const int lane = tid & 31;
    const int rg   = w & 1;
    const int ks   = w >> 1;
    const int r0   = rg * 8;
    const int c0   = lane * CPL;

    unsigned long long acc[4][CPL];
    if (ks == 0) {
#pragma unroll
        for (int c = 0; c < CPL; c++) {
            float b = __ldg(bg + c0 + c);
            unsigned long long bb = pk2(b, b);
#pragma unroll
            for (int p = 0; p < 4; p++) acc[p][c] = bb;
        }
    } else {
#pragma unroll
        for (int p = 0; p < 4; p++)
#pragma unroll
            for (int c = 0; c < CPL; c++) acc[p][c] = 0ull;
    }

    // ---- W prefetch pipeline (1-deep), W via LDG ----
    const float *Wk = Wg + (size_t)(ks * KS) * N + c0;
    float wn[CPL];
    if constexpr (CPL == 8) {
        float4 wa = __ldg(reinterpret_cast<const float4 *>(Wk));
        float4 wb = __ldg(reinterpret_cast<const float4 *>(Wk + 4));
        wn[0]=wa.x; wn[1]=wa.y; wn[2]=wa.z; wn[3]=wa.w;
        wn[4]=wb.x; wn[5]=wb.y; wn[6]=wb.z; wn[7]=wb.w;
    } else {
        float2 wa = __ldg(reinterpret_cast<const float2 *>(Wk));
        wn[0]=wa.x; wn[1]=wa.y;
    }
    Wk += N;

    for (int g = 0; g < NGRP; ++g) {
        const int kbase = ks * KS + g * 8;
        const int swk   = SWR(kbase);       // constant over the 8-group
        const float *p0 = Ain + kbase * TM + ((r0 + 0) ^ swk);
        const float *p1 = Ain + kbase * TM + ((r0 + 2) ^ swk);
        const float *p2 = Ain + kbase * TM + ((r0 + 4) ^ swk);
        const float *p3 = Ain + kbase * TM + ((r0 + 6) ^ swk);

#pragma unroll
        for (int kk = 0; kk < 8; ++kk) {
            // A row-pair broadcasts (uniform LDS.64, immediate offsets)
            unsigned long long ap0 = *reinterpret_cast<const unsigned long long *>(p0 + kk * TM);
            unsigned long long ap1 = *reinterpret_cast<const unsigned long long *>(p1 + kk * TM);
            unsigned long long ap2 = *reinterpret_cast<const unsigned long long *>(p2 + kk * TM);
            unsigned long long ap3 = *reinterpret_cast<const unsigned long long *>(p3 + kk * TM);

            // consume prefetched W, prefetch next
            float wc[CPL];
#pragma unroll
            for (int c = 0; c < CPL; c++) wc[c] = wn[c];

            if (kk < 7 || g + 1 < NGRP) {
                if constexpr (CPL == 8) {
                    float4 wa = __ldg(reinterpret_cast<const float4 *>(Wk));
                    float4 wb = __ldg(reinterpret_cast<const float4 *>(Wk + 4));
                    wn[0]=wa.x; wn[1]=wa.y; wn[2]=wa.z; wn[3]=wa.w;
                    wn[4]=wb.x; wn[5]=wb.y; wn[6]=wb.z; wn[7]=wb.w;
                } else {
                    float2 wa = __ldg(reinterpret_cast<const float2 *>(Wk));
                    wn[0]=wa.x; wn[1]=wa.y;
                }
            }
            Wk += N;

#pragma unroll
            for (int c = 0; c < CPL; c++) {
                unsigned long long wp = pk2(wc[c], wc[c]);
                ffma2(acc[0][c], ap0, wp);
                ffma2(acc[1][c], ap1, wp);
                ffma2(acc[2][c], ap2, wp);
                ffma2(acc[3][c], ap3, wp);
            }
        }
    }

    // ---- partial stores: ks2 -> red0, ks3 -> red1 ----
    if (ks >= 2) {
        float *dst = (ks == 2) ? red0 : red1;
#pragma unroll
        for (int c = 0; c < CPL; c++) {
            const int cc  = c0 + c;
            const int swcv = SWR(cc);
            float *base = dst + cc * TM;
#pragma unroll
            for (int q = 0; q < 2; q++) {
                float a0, a1, a2, a3;
                upk2(acc[2*q][c],   a0, a1);
                upk2(acc[2*q+1][c], a2, a3);
                float4 v; v.x=a0; v.y=a1; v.z=a2; v.w=a3;
                *reinterpret_cast<float4 *>(base + ((r0 + 4*q) ^ swcv)) = v;
            }
        }
    }
    __syncthreads();

    // ---- ks1: acc + red0 + red1 -> red0 ----
    if (ks == 1) {
#pragma unroll
        for (int c = 0; c < CPL; c++) {
            const int cc  = c0 + c;
            const int swcv = SWR(cc);
            float *b0p = red0 + cc * TM;
            const float *b1p = red1 + cc * TM;
#pragma unroll
            for (int q = 0; q < 2; q++) {
                const int off = (r0 + 4*q) ^ swcv;
                float4 v0 = *reinterpret_cast<const float4 *>(b0p + off);
                float4 v1 = *reinterpret_cast<const float4 *>(b1p + off);
                float a0, a1, a2, a3;
                upk2(acc[2*q][c],   a0, a1);
                upk2(acc[2*q+1][c], a2, a3);
                float4 v;
                v.x = a0 + v0.x + v1.x;
                v.y = a1 + v0.y + v1.y;
                v.z = a2 + v0.z + v1.z;
                v.w = a3 + v0.w + v1.w;
                *reinterpret_cast<float4 *>(b0p + off) = v;
            }
        }
    }
    __syncthreads();

    // ---- ks0: acc + red0 (bias already in acc), tanh -> Aout ----
    if (ks == 0) {
#pragma unroll
        for (int c = 0; c < CPL; c++) {
            const int cc  = c0 + c;
            const int swcv = SWR(cc);
            const float *b0p = red0 + cc * TM;
            float *dst = Aout + cc * TM;
#pragma unroll
            for (int q = 0; q < 2; q++) {
                const int off = (r0 + 4*q) ^ swcv;
                float4 v0 = *reinterpret_cast<const float4 *>(b0p + off);
                float a0, a1, a2, a3;
                upk2(acc[2*q][c],   a0, a1);
                upk2(acc[2*q+1][c], a2, a3);
                float4 v;
                v.x = a0 + v0.x;
                v.y = a1 + v0.y;
                v.z = a2 + v0.z;
                v.w = a3 + v0.w;
                if (ACT) {
                    v.x = tanhf(v.x); v.y = tanhf(v.y);
                    v.z = tanhf(v.z); v.w = tanhf(v.w);
                }
                *reinterpret_cast<float4 *>(dst + off) = v;
            }
        }
    }
    __syncthreads();
}

// ---------------------------------------------------------------------------
__global__ void __launch_bounds__(THREADS, 2)
node_kernel(const float *__restrict__ ts, const float *__restrict__ y0,
            const float *__restrict__ W0, const float *__restrict__ b0,
            const float *__restrict__ W1, const float *__restrict__ b1,
            const float *__restrict__ W2, const float *__restrict__ b2,
            const float *__restrict__ W3, const float *__restrict__ b3,
            float *__restrict__ out) {
    extern __shared__ float sm[];
    float *actA = sm;                       // [256][16] row-swizzled
    float *actB = actA + ACT_SIZE;
    float *red0 = actB + ACT_SIZE;
    float *red1 = red0 + RED_SIZE;
    float *zbuf = red1 + RED_SIZE;          // [64][16] row-swizzled
    float *ybuf = zbuf + ZK_SIZE;
    float *kbuf = ybuf + ZK_SIZE;           // 6 * [64][16]

    const int tid = threadIdx.x;
    const int cta = blockIdx.x;

    // ingest y0 (row-major) -> ybuf (transposed, row-swizzled); emit out[0]
    {
        const float *y0c = y0 + (size_t)cta * TM * DIM;
        float *o0 = out + (size_t)cta * TM * DIM;
        for (int i = tid; i < TM * DIM; i += THREADS) {
            const int r = i >> 6;       // 0..15
            const int d = i & 63;
            float v = __ldg(y0c + i);
            ybuf[d * TM + (r ^ SWR(d))] = v;
            o0[i] = v;
        }
    }
    __syncthreads();

    for (int t = 1; t < NTT; ++t) {
        const float h = __ldg(ts + t) - __ldg(ts + t - 1);

        for (int s = 0; s < 6; ++s) {
            const float *zin;
            if (s == 0) {
                zin = ybuf;
            } else {
                // z = y + h * sum_{j<s} A[s][j]*k_j (elementwise, same layout)
                float4 *zb = reinterpret_cast<float4 *>(zbuf);
                const float4 *yb = reinterpret_cast<const float4 *>(ybuf);
                for (int i = tid; i < ZK_SIZE / 4; i += THREADS) {
                    float4 v = yb[i];
                    for (int j = 0; j < s; j++) {
                        float c = h * c_A[s][j];
                        float4 kv = reinterpret_cast<const float4 *>(kbuf + j * ZK_SIZE)[i];
                        v.x += c * kv.x; v.y += c * kv.y;
                        v.z += c * kv.z; v.w += c * kv.w;
                    }
                    zb[i] = v;
                }
                __syncthreads();
                zin = zbuf;
            }

            layerT<DIM,   WIDTH, true >(zin,  actA, W0, b0, red0, red1);
            layerT<WIDTH, WIDTH, true >(actA, actB, W1, b1, red0, red1);
            layerT<WIDTH, WIDTH, true >(actB, actA, W2, b2, red0, red1);
            layerT<WIDTH, DIM,   false>(actA, kbuf + s * ZK_SIZE, W3, b3, red0, red1);
        }

        // y += h * sum_j B[j]*k_j (elementwise)
        {
            float4 *yb = reinterpret_cast<float4 *>(ybuf);
            for (int i = tid; i < ZK_SIZE / 4; i += THREADS) {
                float4 v = yb[i];
#pragma unroll
                for (int j = 0; j < 6; j++) {
                    float c = h * c_B[j];
                    float4 kv = reinterpret_cast<const float4 *>(kbuf + j * ZK_SIZE)[i];
                    v.x += c * kv.x; v.y += c * kv.y;
                    v.z += c * kv.z; v.w += c * kv.w;
                }
                yb[i] = v;
            }
        }
        __syncthreads();

        // store out[t] (row-major, coalesced) from swizzled ybuf
        {
            float *outc = out + (size_t)t * (BATCH * DIM) + (size_t)cta * TM * DIM;
            for (int i = tid; i < TM * DIM; i += THREADS) {
                const int r = i >> 6;
                const int d = i & 63;
                outc[i] = ybuf[d * TM + (r ^ SWR(d))];
            }
        }
        __syncthreads();
    }
}

// ---------------------------------------------------------------------------
extern "C" void kernel_launch(void *const *d_in, const int *in_sizes, int n_in,
                              void *d_out, int out_size) {
    const float *ts = (const float *)d_in[0];
    const float *y0 = (const float *)d_in[1];
    const float *W0 = (const float *)d_in[2];
    const float *b0 = (const float *)d_in[3];
    const float *W1 = (const float *)d_in[4];
    const float *b1 = (const float *)d_in[5];
    const float *W2 = (const float *)d_in[6];
    const float *b2 = (const float *)d_in[7];
    const float *W3 = (const float *)d_in[8];
    const float *b3 = (const float *)d_in[9];
    float *out = (float *)d_out;

    cudaFuncSetAttribute(node_kernel,
                         cudaFuncAttributeMaxDynamicSharedMemorySize, SMEM_BYTES);
    node_kernel<<<NCTA, THREADS, SMEM_BYTES>>>(ts, y0, W0, b0, W1, b1,
                                               W2, b2, W3, b3, out);
}

// round 15
// speedup vs baseline: 1.4172x; 1.4172x over previous
#include <cuda_runtime.h>
#include <cstdint>
#include <math.h>

// ---------------------------------------------------------------------------
// NeuralODE Tsit5 — persistent-CTA kernel, round 14: tf32 tensor cores.
// Scalar fp32 roofline (~64 FMA/cyc/SM) reached at 22.8ms; this moves the
// GEMMs to mma.sync.m16n8k8.tf32 with 3-pass precision splitting:
//   x = xh + xl, W = Wh + Wl;  x*W ~= xh*Wh + xl*Wh + xh*Wl  (err ~2^-21)
// - W pre-split & packed in B-fragment order (prologue kernel, LDG.128/lane)
// - activations kept as hi/lo fp32(tf32-bits) pairs in SMEM, padded strides
//   (68 / 260: stride%32==4 -> 4g+t bank map, conflict-free fragment loads)
// - epilogue: bias + tanh + re-split to hi/lo
// ---------------------------------------------------------------------------

#define BATCH   4096
#define DIM     64
#define WIDTH   256
#define NTT     101
#define TM      32
#define NCTA    128
#define THREADS 512

#define AST 260                 // activation stride (256 + 4)
#define ZST 68                  // z/y/k stride (64 + 4)
#define ACT_F (TM * AST)        // 8320 floats
#define ZK_F  (TM * ZST)        // 2176 floats

// smem: actA(h,l) + actB(h,l) + z(h,l) + y + 6*k
#define SMEM_FLOATS (4*ACT_F + 9*ZK_F)
#define SMEM_BYTES  (SMEM_FLOATS * 4)   // 211456 B

// packed, pre-split weights in B-fragment order:
// entry e = (layer_base + tile*32 + lane), value = {b0_hi, b1_hi, b0_lo, b1_lo}
// tiles: L0 8kt x 32nt, L1/L2 32 x 32, L3 32kt x 8nt
#define BPK_L0 0
#define BPK_L1 8192
#define BPK_L2 40960
#define BPK_L3 73728
#define BPK_TOTAL 81920
__device__ float4 g_Bpk[BPK_TOTAL];

// Tsit5 tableau
__constant__ float c_A[6][5] = {
    {0.f, 0.f, 0.f, 0.f, 0.f},
    {0.161f, 0.f, 0.f, 0.f, 0.f},
    {-0.008480655492356989f, 0.335480655492357f, 0.f, 0.f, 0.f},
    {2.8971530571054935f, -6.359448489975075f, 4.3622954328695815f, 0.f, 0.f},
    {5.325864828439257f, -11.748883564062828f, 7.4955393428898365f, -0.09249506636175525f, 0.f},
    {5.86145544294642f, -12.92096931784711f, 8.159367898576159f, -0.071584973281401f, -0.028269050394068383f}
};
__constant__ float c_B[6] = {
    0.09646076681806523f, 0.01f, 0.4798896504144996f,
    1.379008574103742f, -3.290069515436081f, 2.324710524099774f
};

// ---- tf32 helpers ----
__device__ __forceinline__ unsigned f2tf(float x) {
    unsigned r;
    asm("cvt.rna.tf32.f32 %0, %1;" : "=r"(r) : "f"(x));
    return r;
}

// mma.sync m16n8k8 tf32: C(16x8,f32) += A(16x8) * B(8x8)
__device__ __forceinline__ void mma8(float *c, const unsigned *a,
                                     unsigned b0, unsigned b1) {
    asm("mma.sync.aligned.m16n8k8.row.col.f32.tf32.tf32.f32 "
        "{%0,%1,%2,%3},{%4,%5,%6,%7},{%8,%9},{%0,%1,%2,%3};"
        : "+f"(c[0]), "+f"(c[1]), "+f"(c[2]), "+f"(c[3])
        : "r"(a[0]), "r"(a[1]), "r"(a[2]), "r"(a[3]), "r"(b0), "r"(b1));
}

// ---------------------------------------------------------------------------
// Prologue: split each W into tf32 hi/lo and pack in B-fragment order.
// B-frag (m16n8k8, col-major B = k x n): lane(t=lane&3,g=lane>>2):
//   b0 = W[kt*8+t][nt*8+g],  b1 = W[kt*8+t+4][nt*8+g]
// ---------------------------------------------------------------------------
__global__ void pack_kernel(const float *__restrict__ W0, const float *__restrict__ W1,
                            const float *__restrict__ W2, const float *__restrict__ W3) {
    int e = blockIdx.x * blockDim.x + threadIdx.x;
    if (e >= BPK_TOTAL) return;
    const float *W;
    int base, N;
    if (e < BPK_L1)       { W = W0; base = BPK_L0; N = 256; }
    else if (e < BPK_L2)  { W = W1; base = BPK_L1; N = 256; }
    else if (e < BPK_L3)  { W = W2; base = BPK_L2; N = 256; }
    else                  { W = W3; base = BPK_L3; N = 64;  }
    int r    = e - base;
    int tile = r >> 5;
    int lane = r & 31;
    int nt, kt;
    if (N == 256) { nt = tile & 31; kt = tile >> 5; }
    else          { nt = tile & 7;  kt = tile >> 3; }
    int t = lane & 3, g = lane >> 2;
    int k0 = kt * 8 + t, n = nt * 8 + g;
    float b0 = W[(size_t)k0 * N + n];
    float b1 = W[(size_t)(k0 + 4) * N + n];
    float h0 = __uint_as_float(f2tf(b0));
    float h1 = __uint_as_float(f2tf(b1));
    float l0 = __uint_as_float(f2tf(b0 - h0));
    float l1 = __uint_as_float(f2tf(b1 - h1));
    g_Bpk[e] = make_float4(h0, h1, l0, l1);
}

// ---------------------------------------------------------------------------
// Layer with N=256 output. 16 warps: mt = w&1 (M 16-tile), ng = w>>1 (4 n-tiles).
// Inputs: hi/lo activation arrays (tf32 bits), stride inst.
// Output: bias + (tanh) + hi/lo split into outHi/outLo (stride AST).
// ---------------------------------------------------------------------------
template <int K, bool ACT>
__device__ __forceinline__ void layer256(const float *inHi, const float *inLo, int inst,
                                         float *outHi, float *outLo,
                                         const float4 *Bp0, const float *__restrict__ bias) {
    constexpr int KT = K / 8;
    const int tid  = threadIdx.x;
    const int w    = tid >> 5;
    const int lane = tid & 31;
    const int t    = lane & 3, g = lane >> 2;
    const int mt   = w & 1,   ng = w >> 1;

    const float *pH0 = inHi + (mt * 16 + g) * inst + t;
    const float *pH1 = pH0 + 8 * inst;
    const float *pL0 = inLo + (mt * 16 + g) * inst + t;
    const float *pL1 = pL0 + 8 * inst;
    const float4 *Bp = Bp0 + (ng * 4) * 32 + lane;

    float C[4][4];
#pragma unroll
    for (int j = 0; j < 4; j++) { C[j][0] = C[j][1] = C[j][2] = C[j][3] = 0.f; }

#pragma unroll 4
    for (int kt = 0; kt < KT; ++kt) {
        const int kc = kt * 8;
        unsigned aH[4], aL[4];
        aH[0] = __float_as_uint(pH0[kc]);
        aH[1] = __float_as_uint(pH1[kc]);
        aH[2] = __float_as_uint(pH0[kc + 4]);
        aH[3] = __float_as_uint(pH1[kc + 4]);
        aL[0] = __float_as_uint(pL0[kc]);
        aL[1] = __float_as_uint(pL1[kc]);
        aL[2] = __float_as_uint(pL0[kc + 4]);
        aL[3] = __float_as_uint(pL1[kc + 4]);
#pragma unroll
        for (int j = 0; j < 4; j++) {
            float4 b = __ldg(Bp + kt * 1024 + j * 32);
            unsigned bx = __float_as_uint(b.x), by = __float_as_uint(b.y);
            unsigned bz = __float_as_uint(b.z), bw = __float_as_uint(b.w);
            mma8(C[j], aH, bx, by);   // hi*hi
            mma8(C[j], aL, bx, by);   // lo*hi
            mma8(C[j], aH, bz, bw);   // hi*lo
        }
    }

    // epilogue: bias + tanh + split. C lane map: c0,c1: row g, cols 2t,2t+1;
    // c2,c3: row g+8. tile j cols base (ng*4+j)*8.
    const int row0 = mt * 16 + g;
#pragma unroll
    for (int j = 0; j < 4; j++) {
        const int col = (ng * 4 + j) * 8 + 2 * t;
        float2 bv = *reinterpret_cast<const float2 *>(bias + col);
        float x0 = C[j][0] + bv.x, x1 = C[j][1] + bv.y;
        float x2 = C[j][2] + bv.x, x3 = C[j][3] + bv.y;
        if (ACT) { x0 = tanhf(x0); x1 = tanhf(x1); x2 = tanhf(x2); x3 = tanhf(x3); }
        float h0 = __uint_as_float(f2tf(x0));
        float h1 = __uint_as_float(f2tf(x1));
        float h2 = __uint_as_float(f2tf(x2));
        float h3 = __uint_as_float(f2tf(x3));
        float l0 = __uint_as_float(f2tf(x0 - h0));
        float l1 = __uint_as_float(f2tf(x1 - h1));
        float l2 = __uint_as_float(f2tf(x2 - h2));
        float l3 = __uint_as_float(f2tf(x3 - h3));
        *reinterpret_cast<float2 *>(outHi + row0 * AST + col)       = make_float2(h0, h1);
        *reinterpret_cast<float2 *>(outLo + row0 * AST + col)       = make_float2(l0, l1);
        *reinterpret_cast<float2 *>(outHi + (row0 + 8) * AST + col) = make_float2(h2, h3);
        *reinterpret_cast<float2 *>(outLo + (row0 + 8) * AST + col) = make_float2(l2, l3);
    }
    __syncthreads();
}

// ---------------------------------------------------------------------------
// Layer with N=64 output (K=256, no activation): k-stage producer.
// 16 warps: mt = w&1, nt = w>>1 (one n-tile each). Output fp32, stride ZST.
// ---------------------------------------------------------------------------
__device__ __forceinline__ void layer64(const float *inHi, const float *inLo,
                                        float *kout,
                                        const float4 *Bp0, const float *__restrict__ bias) {
    const int tid  = threadIdx.x;
    const int w    = tid >> 5;
    const int lane = tid & 31;
    const int t    = lane & 3, g = lane >> 2;
    const int mt   = w & 1,   nt = w >> 1;

    const float *pH0 = inHi + (mt * 16 + g) * AST + t;
    const float *pH1 = pH0 + 8 * AST;
    const float *pL0 = inLo + (mt * 16 + g) * AST + t;
    const float *pL1 = pL0 + 8 * AST;
    const float4 *Bp = Bp0 + nt * 32 + lane;

    float C[4] = {0.f, 0.f, 0.f, 0.f};

#pragma unroll 4
    for (int kt = 0; kt < 32; ++kt) {
        const int kc = kt * 8;
        unsigned aH[4], aL[4];
        aH[0] = __float_as_uint(pH0[kc]);
        aH[1] = __float_as_uint(pH1[kc]);
        aH[2] = __float_as_uint(pH0[kc + 4]);
        aH[3] = __float_as_uint(pH1[kc + 4]);
        aL[0] = __float_as_uint(pL0[kc]);
        aL[1] = __float_as_uint(pL1[kc]);
        aL[2] = __float_as_uint(pL0[kc + 4]);
        aL[3] = __float_as_uint(pL1[kc + 4]);
        float4 b = __ldg(Bp + kt * 256);
        unsigned bx = __float_as_uint(b.x), by = __float_as_uint(b.y);
        unsigned bz = __float_as_uint(b.z), bw = __float_as_uint(b.w);
        mma8(C, aH, bx, by);
        mma8(C, aL, bx, by);
        mma8(C, aH, bz, bw);
    }

    const int col  = nt * 8 + 2 * t;
    const int row0 = mt * 16 + g;
    float2 bv = *reinterpret_cast<const float2 *>(bias + col);
    *reinterpret_cast<float2 *>(kout + row0 * ZST + col) =
        make_float2(C[0] + bv.x, C[1] + bv.y);
    *reinterpret_cast<float2 *>(kout + (row0 + 8) * ZST + col) =
        make_float2(C[2] + bv.x, C[3] + bv.y);
    __syncthreads();
}

// ---------------------------------------------------------------------------
__global__ void __launch_bounds__(THREADS, 1)
node_kernel(const float *__restrict__ ts, const float *__restrict__ y0,
            const float *__restrict__ b0, const float *__restrict__ b1,
            const float *__restrict__ b2, const float *__restrict__ b3,
            float *__restrict__ out) {
    extern __shared__ float sm[];
    float *actAH = sm;
    float *actAL = actAH + ACT_F;
    float *actBH = actAL + ACT_F;
    float *actBL = actBH + ACT_F;
    float *zH    = actBL + ACT_F;
    float *zL    = zH + ZK_F;
    float *ybuf  = zL + ZK_F;
    float *kbuf  = ybuf + ZK_F;      // 6 * ZK_F

    const int tid = threadIdx.x;
    const int cta = blockIdx.x;

    const float4 *BpL0 = g_Bpk + BPK_L0;
    const float4 *BpL1 = g_Bpk + BPK_L1;
    const float4 *BpL2 = g_Bpk + BPK_L2;
    const float4 *BpL3 = g_Bpk + BPK_L3;

    // ingest y0 (row-major) -> ybuf (stride ZST); emit out[0]
    {
        const float *y0c = y0 + (size_t)cta * TM * DIM;
        float *o0 = out + (size_t)cta * TM * DIM;
        for (int i = tid; i < TM * DIM; i += THREADS) {
            const int r = i >> 6, d = i & 63;
            float v = __ldg(y0c + i);
            ybuf[r * ZST + d] = v;
            o0[i] = v;
        }
    }
    __syncthreads();

    for (int tt = 1; tt < NTT; ++tt) {
        const float h = __ldg(ts + tt) - __ldg(ts + tt - 1);

        for (int s = 0; s < 6; ++s) {
            // z = y + h*sum_{j<s} A[s][j]*k_j, then split to tf32 hi/lo
            for (int i = tid; i < TM * DIM; i += THREADS) {
                const int r = i >> 6, d = i & 63;
                const int idx = r * ZST + d;
                float v = ybuf[idx];
                for (int j = 0; j < s; j++)
                    v += (h * c_A[s][j]) * kbuf[j * ZK_F + idx];
                float hv = __uint_as_float(f2tf(v));
                zH[idx] = hv;
                zL[idx] = __uint_as_float(f2tf(v - hv));
            }
            __syncthreads();

            layer256<DIM,   true>(zH,    zL,    ZST, actAH, actAL, BpL0, b0);
            layer256<WIDTH, true>(actAH, actAL, AST, actBH, actBL, BpL1, b1);
            layer256<WIDTH, true>(actBH, actBL, AST, actAH, actAL, BpL2, b2);
            layer64(actAH, actAL, kbuf + s * ZK_F, BpL3, b3);
        }

        // y += h*sum_j B[j]*k_j ; write out[tt] (coalesced)
        {
            float *outc = out + (size_t)tt * (BATCH * DIM) + (size_t)cta * TM * DIM;
            for (int i = tid; i < TM * DIM; i += THREADS) {
                const int r = i >> 6, d = i & 63;
                const int idx = r * ZST + d;
                float v = ybuf[idx];
#pragma unroll
                for (int j = 0; j < 6; j++)
                    v += (h * c_B[j]) * kbuf[j * ZK_F + idx];
                ybuf[idx] = v;
                outc[i] = v;
            }
        }
        __syncthreads();
    }
}

// ---------------------------------------------------------------------------
extern "C" void kernel_launch(void *const *d_in, const int *in_sizes, int n_in,
                              void *d_out, int out_size) {
    const float *ts = (const float *)d_in[0];
    const float *y0 = (const float *)d_in[1];
    const float *W0 = (const float *)d_in[2];
    const float *b0 = (const float *)d_in[3];
    const float *W1 = (const float *)d_in[4];
    const float *b1 = (const float *)d_in[5];
    const float *W2 = (const float *)d_in[6];
    const float *b2 = (const float *)d_in[7];
    const float *W3 = (const float *)d_in[8];
    const float *b3 = (const float *)d_in[9];
    float *out = (float *)d_out;

    pack_kernel<<<(BPK_TOTAL + 255) / 256, 256>>>(W0, W1, W2, W3);

    cudaFuncSetAttribute(node_kernel,
                         cudaFuncAttributeMaxDynamicSharedMemorySize, SMEM_BYTES);
    node_kernel<<<NCTA, THREADS, SMEM_BYTES>>>(ts, y0, b0, b1, b2, b3, out);
}

// round 16
// speedup vs baseline: 2.4775x; 1.7482x over previous
#include <cuda_runtime.h>
#include <cuda_bf16.h>
#include <cstdint>
#include <math.h>

// ---------------------------------------------------------------------------
// NeuralODE Tsit5 — persistent-CTA kernel, round 15: bf16x3 tensor cores.
// tf32x3 (16.9ms) was L1-bound; bf16 m16n8k16 halves BOTH L1 wavefronts and
// tensor time per FLOP. 3-pass split: x*W ~= xh*Wh + xl*Wh + xh*Wl,
// per-GEMM err ~2^-16 (expected final ~1e-4 << 1e-3).
// - W pre-split & packed in B-fragment order (uint4/lane per k16-tile)
// - activations as bf16 hi/lo in SMEM, stride 264 (row 528B = 16 mod 128:
//   conflict-free fragment loads, 1 wf per b32 load)
// - y/k state kept fp32 (stride 68); z split to bf16 each stage
// ---------------------------------------------------------------------------

#define BATCH   4096
#define DIM     64
#define WIDTH   256
#define NTT     101
#define TM      32
#define NCTA    128
#define THREADS 512

#define AST2 264                // act stride in bf16 elems (528B row)
#define ZB2  72                 // z hi/lo stride in bf16 elems (144B row)
#define ZST  68                 // y/k fp32 stride

#define ACT_E (TM * AST2)       // 8448 bf16
#define ZB_E  (TM * ZB2)        // 2304 bf16
#define ZK_F  (TM * ZST)        // 2176 floats

// smem bytes: 4 act arrays + 2 z arrays (bf16) + y + 6k (fp32)
#define SMEM_BYTES ((4*ACT_E + 2*ZB_E) * 2 + 7 * ZK_F * 4)   // 137728

// packed pre-split weights, B-fragment order, one uint4 per (tile,lane):
//   {b0_hi, b1_hi, b0_lo, b1_lo}, each b32 = 2 bf16 (k, k+1)
// tile index = kt*NT + nt ; entry = base + tile*32 + lane
#define BPK_L0 0                 // KT=4,  NT=32 -> 4096
#define BPK_L1 4096              // KT=16, NT=32 -> 16384
#define BPK_L2 20480             // KT=16, NT=32 -> 16384
#define BPK_L3 36864             // KT=16, NT=8  -> 4096
#define BPK_TOTAL 40960
__device__ uint4 g_Bpk[BPK_TOTAL];

// Tsit5 tableau
__constant__ float c_A[6][5] = {
    {0.f, 0.f, 0.f, 0.f, 0.f},
    {0.161f, 0.f, 0.f, 0.f, 0.f},
    {-0.008480655492356989f, 0.335480655492357f, 0.f, 0.f, 0.f},
    {2.8971530571054935f, -6.359448489975075f, 4.3622954328695815f, 0.f, 0.f},
    {5.325864828439257f, -11.748883564062828f, 7.4955393428898365f, -0.09249506636175525f, 0.f},
    {5.86145544294642f, -12.92096931784711f, 8.159367898576159f, -0.071584973281401f, -0.028269050394068383f}
};
__constant__ float c_B[6] = {
    0.09646076681806523f, 0.01f, 0.4798896504144996f,
    1.379008574103742f, -3.290069515436081f, 2.324710524099774f
};

// ---- bf16 helpers ----
__device__ __forceinline__ unsigned pack_bf2(float a, float b) {
    __nv_bfloat16 ha = __float2bfloat16(a);
    __nv_bfloat16 hb = __float2bfloat16(b);
    return (unsigned)__bfloat16_as_ushort(ha) |
           ((unsigned)__bfloat16_as_ushort(hb) << 16);
}
__device__ __forceinline__ void split_bf(float x, __nv_bfloat16 &h, __nv_bfloat16 &l) {
    h = __float2bfloat16(x);
    l = __float2bfloat16(x - __bfloat162float(h));
}

// mma.sync m16n8k16 bf16: C(16x8,f32) += A(16x16) * B(16x8)
__device__ __forceinline__ void mma16(float *c, unsigned a0, unsigned a1,
                                      unsigned a2, unsigned a3,
                                      unsigned b0, unsigned b1) {
    asm("mma.sync.aligned.m16n8k16.row.col.f32.bf16.bf16.f32 "
        "{%0,%1,%2,%3},{%4,%5,%6,%7},{%8,%9},{%0,%1,%2,%3};"
        : "+f"(c[0]), "+f"(c[1]), "+f"(c[2]), "+f"(c[3])
        : "r"(a0), "r"(a1), "r"(a2), "r"(a3), "r"(b0), "r"(b1));
}

// ---------------------------------------------------------------------------
// Prologue: split W into bf16 hi/lo, pack in m16n8k16 B-fragment order.
// lane(t=lane&3, g=lane>>2): b0 = {B[k0][n],B[k0+1][n]}, b1 = {B[k0+8][n],B[k0+9][n]},
// k0 = kt*16 + 2t, n = nt*8 + g.
// ---------------------------------------------------------------------------
__global__ void pack_kernel(const float *__restrict__ W0, const float *__restrict__ W1,
                            const float *__restrict__ W2, const float *__restrict__ W3) {
    int e = blockIdx.x * blockDim.x + threadIdx.x;
    if (e >= BPK_TOTAL) return;
    const float *W;
    int base, N, NT;
    if (e < BPK_L1)      { W = W0; base = BPK_L0; N = 256; NT = 32; }
    else if (e < BPK_L2) { W = W1; base = BPK_L1; N = 256; NT = 32; }
    else if (e < BPK_L3) { W = W2; base = BPK_L2; N = 256; NT = 32; }
    else                 { W = W3; base = BPK_L3; N = 64;  NT = 8;  }
    int r = e - base;
    int tile = r >> 5, lane = r & 31;
    int kt = tile / NT, nt = tile % NT;
    int t = lane & 3, g = lane >> 2;
    int n  = nt * 8 + g;
    int k0 = kt * 16 + 2 * t;

    float w00 = W[(size_t)(k0    ) * N + n];
    float w01 = W[(size_t)(k0 + 1) * N + n];
    float w10 = W[(size_t)(k0 + 8) * N + n];
    float w11 = W[(size_t)(k0 + 9) * N + n];

    __nv_bfloat16 h00, l00, h01, l01, h10, l10, h11, l11;
    split_bf(w00, h00, l00);
    split_bf(w01, h01, l01);
    split_bf(w10, h10, l10);
    split_bf(w11, h11, l11);

    uint4 v;
    v.x = (unsigned)__bfloat16_as_ushort(h00) | ((unsigned)__bfloat16_as_ushort(h01) << 16);
    v.y = (unsigned)__bfloat16_as_ushort(h10) | ((unsigned)__bfloat16_as_ushort(h11) << 16);
    v.z = (unsigned)__bfloat16_as_ushort(l00) | ((unsigned)__bfloat16_as_ushort(l01) << 16);
    v.w = (unsigned)__bfloat16_as_ushort(l10) | ((unsigned)__bfloat16_as_ushort(l11) << 16);
    g_Bpk[e] = v;
}

// ---------------------------------------------------------------------------
// Layer with N=256 output. 16 warps: mt = w&1 (M 16-tile), ng = w>>1 (4 n-tiles).
// Inputs: bf16 hi/lo activation arrays, stride inst (bf16 elems).
// Output: bias + (tanh) + bf16 hi/lo split, stride AST2.
// ---------------------------------------------------------------------------
template <int K, bool ACT>
__device__ __forceinline__ void layer256(const __nv_bfloat16 *inH, const __nv_bfloat16 *inL,
                                         int inst,
                                         __nv_bfloat16 *outH, __nv_bfloat16 *outL,
                                         const uint4 *Bp0, const float *__restrict__ bias) {
    constexpr int KT = K / 16;
    const int tid  = threadIdx.x;
    const int w    = tid >> 5;
    const int lane = tid & 31;
    const int t    = lane & 3, g = lane >> 2;
    const int mt   = w & 1,   ng = w >> 1;

    const __nv_bfloat16 *pH = inH + (mt * 16 + g) * inst + 2 * t;
    const __nv_bfloat16 *pL = inL + (mt * 16 + g) * inst + 2 * t;
    const int roff = 8 * inst;
    const uint4 *Bp = Bp0 + (ng * 4) * 32 + lane;

    float C[4][4];
#pragma unroll
    for (int j = 0; j < 4; j++) { C[j][0] = C[j][1] = C[j][2] = C[j][3] = 0.f; }

#pragma unroll 4
    for (int kt = 0; kt < KT; ++kt) {
        const int kc = kt * 16;
        unsigned aH0 = *reinterpret_cast<const unsigned *>(pH + kc);
        unsigned aH1 = *reinterpret_cast<const unsigned *>(pH + kc + roff);
        unsigned aH2 = *reinterpret_cast<const unsigned *>(pH + kc + 8);
        unsigned aH3 = *reinterpret_cast<const unsigned *>(pH + kc + roff + 8);
        unsigned aL0 = *reinterpret_cast<const unsigned *>(pL + kc);
        unsigned aL1 = *reinterpret_cast<const unsigned *>(pL + kc + roff);
        unsigned aL2 = *reinterpret_cast<const unsigned *>(pL + kc + 8);
        unsigned aL3 = *reinterpret_cast<const unsigned *>(pL + kc + roff + 8);
#pragma unroll
        for (int j = 0; j < 4; j++) {
            uint4 b = __ldg(Bp + kt * 1024 + j * 32);
            mma16(C[j], aH0, aH1, aH2, aH3, b.x, b.y);   // hi*hi
            mma16(C[j], aL0, aL1, aL2, aL3, b.x, b.y);   // lo*hi
            mma16(C[j], aH0, aH1, aH2, aH3, b.z, b.w);   // hi*lo
        }
    }

    // epilogue: bias + tanh + bf16 split.
    // C lane map: c0,c1: row g cols 2t,2t+1; c2,c3: row g+8.
    const int row0 = mt * 16 + g;
#pragma unroll
    for (int j = 0; j < 4; j++) {
        const int col = (ng * 4 + j) * 8 + 2 * t;
        float2 bv = *reinterpret_cast<const float2 *>(bias + col);
        float x0 = C[j][0] + bv.x, x1 = C[j][1] + bv.y;
        float x2 = C[j][2] + bv.x, x3 = C[j][3] + bv.y;
        if (ACT) { x0 = tanhf(x0); x1 = tanhf(x1); x2 = tanhf(x2); x3 = tanhf(x3); }
        __nv_bfloat16 h0, l0, h1, l1, h2, l2, h3, l3;
        split_bf(x0, h0, l0); split_bf(x1, h1, l1);
        split_bf(x2, h2, l2); split_bf(x3, h3, l3);
        *reinterpret_cast<unsigned *>(outH + row0 * AST2 + col) =
            (unsigned)__bfloat16_as_ushort(h0) | ((unsigned)__bfloat16_as_ushort(h1) << 16);
        *reinterpret_cast<unsigned *>(outL + row0 * AST2 + col) =
            (unsigned)__bfloat16_as_ushort(l0) | ((unsigned)__bfloat16_as_ushort(l1) << 16);
        *reinterpret_cast<unsigned *>(outH + (row0 + 8) * AST2 + col) =
            (unsigned)__bfloat16_as_ushort(h2) | ((unsigned)__bfloat16_as_ushort(h3) << 16);
        *reinterpret_cast<unsigned *>(outL + (row0 + 8) * AST2 + col) =
            (unsigned)__bfloat16_as_ushort(l2) | ((unsigned)__bfloat16_as_ushort(l3) << 16);
    }
    __syncthreads();
}

// ---------------------------------------------------------------------------
// Layer with N=64 output (K=256, no activation): k-stage producer, fp32 out.
// 16 warps: mt = w&1, nt = w>>1 (one n-tile each). Output stride ZST.
// ---------------------------------------------------------------------------
__device__ __forceinline__ void layer64(const __nv_bfloat16 *inH, const __nv_bfloat16 *inL,
                                        float *kout,
                                        const uint4 *Bp0, const float *__restrict__ bias) {
    const int tid  = threadIdx.x;
    const int w    = tid >> 5;
    const int lane = tid & 31;
    const int t    = lane & 3, g = lane >> 2;
    const int mt   = w & 1,   nt = w >> 1;

    const __nv_bfloat16 *pH = inH + (mt * 16 + g) * AST2 + 2 * t;
    const __nv_bfloat16 *pL = inL + (mt * 16 + g) * AST2 + 2 * t;
    const int roff = 8 * AST2;
    const uint4 *Bp = Bp0 + nt * 32 + lane;

    float C[4] = {0.f, 0.f, 0.f, 0.f};

#pragma unroll 4
    for (int kt = 0; kt < 16; ++kt) {
        const int kc = kt * 16;
        unsigned aH0 = *reinterpret_cast<const unsigned *>(pH + kc);
        unsigned aH1 = *reinterpret_cast<const unsigned *>(pH + kc + roff);
        unsigned aH2 = *reinterpret_cast<const unsigned *>(pH + kc + 8);
        unsigned aH3 = *reinterpret_cast<const unsigned *>(pH + kc + roff + 8);
        unsigned aL0 = *reinterpret_cast<const unsigned *>(pL + kc);
        unsigned aL1 = *reinterpret_cast<const unsigned *>(pL + kc + roff);
        unsigned aL2 = *reinterpret_cast<const unsigned *>(pL + kc + 8);
        unsigned aL3 = *reinterpret_cast<const unsigned *>(pL + kc + roff + 8);
        uint4 b = __ldg(Bp + kt * 256);
        mma16(C, aH0, aH1, aH2, aH3, b.x, b.y);
        mma16(C, aL0, aL1, aL2, aL3, b.x, b.y);
        mma16(C, aH0, aH1, aH2, aH3, b.z, b.w);
    }

    const int col  = nt * 8 + 2 * t;
    const int row0 = mt * 16 + g;
    float2 bv = *reinterpret_cast<const float2 *>(bias + col);
    *reinterpret_cast<float2 *>(kout + row0 * ZST + col) =
        make_float2(C[0] + bv.x, C[1] + bv.y);
    *reinterpret_cast<float2 *>(kout + (row0 + 8) * ZST + col) =
        make_float2(C[2] + bv.x, C[3] + bv.y);
    __syncthreads();
}

// ---------------------------------------------------------------------------
__global__ void __launch_bounds__(THREADS, 1)
node_kernel(const float *__restrict__ ts, const float *__restrict__ y0,
            const float *__restrict__ b0, const float *__restrict__ b1,
            const float *__restrict__ b2, const float *__restrict__ b3,
            float *__restrict__ out) {
    extern __shared__ char smc[];
    __nv_bfloat16 *actAH = reinterpret_cast<__nv_bfloat16 *>(smc);
    __nv_bfloat16 *actAL = actAH + ACT_E;
    __nv_bfloat16 *actBH = actAL + ACT_E;
    __nv_bfloat16 *actBL = actBH + ACT_E;
    __nv_bfloat16 *zH    = actBL + ACT_E;
    __nv_bfloat16 *zL    = zH + ZB_E;
    float *ybuf = reinterpret_cast<float *>(zL + ZB_E);
    float *kbuf = ybuf + ZK_F;       // 6 * ZK_F

    const int tid = threadIdx.x;
    const int cta = blockIdx.x;

    const uint4 *BpL0 = g_Bpk + BPK_L0;
    const uint4 *BpL1 = g_Bpk + BPK_L1;
    const uint4 *BpL2 = g_Bpk + BPK_L2;
    const uint4 *BpL3 = g_Bpk + BPK_L3;

    // ingest y0 (row-major) -> ybuf (fp32, stride ZST); emit out[0]
    {
        const float *y0c = y0 + (size_t)cta * TM * DIM;
        float *o0 = out + (size_t)cta * TM * DIM;
        for (int i = tid; i < TM * DIM; i += THREADS) {
            const int r = i >> 6, d = i & 63;
            float v = __ldg(y0c + i);
            ybuf[r * ZST + d] = v;
            o0[i] = v;
        }
    }
    __syncthreads();

    for (int tt = 1; tt < NTT; ++tt) {
        const float h = __ldg(ts + tt) - __ldg(ts + tt - 1);

        for (int s = 0; s < 6; ++s) {
            // z = y + h*sum_{j<s} A[s][j]*k_j, split into bf16 hi/lo
            for (int i = tid; i < TM * DIM; i += THREADS) {
                const int r = i >> 6, d = i & 63;
                float v = ybuf[r * ZST + d];
                for (int j = 0; j < s; j++)
                    v += (h * c_A[s][j]) * kbuf[j * ZK_F + r * ZST + d];
                __nv_bfloat16 hv, lv;
                split_bf(v, hv, lv);
                zH[r * ZB2 + d] = hv;
                zL[r * ZB2 + d] = lv;
            }
            __syncthreads();

            layer256<DIM,   true>(zH,    zL,    ZB2,  actAH, actAL, BpL0, b0);
            layer256<WIDTH, true>(actAH, actAL, AST2, actBH, actBL, BpL1, b1);
            layer256<WIDTH, true>(actBH, actBL, AST2, actAH, actAL, BpL2, b2);
            layer64(actAH, actAL, kbuf + s * ZK_F, BpL3, b3);
        }

        // y += h*sum_j B[j]*k_j ; write out[tt] (coalesced)
        {
            float *outc = out + (size_t)tt * (BATCH * DIM) + (size_t)cta * TM * DIM;
            for (int i = tid; i < TM * DIM; i += THREADS) {
                const int r = i >> 6, d = i & 63;
                const int idx = r * ZST + d;
                float v = ybuf[idx];
#pragma unroll
                for (int j = 0; j < 6; j++)
                    v += (h * c_B[j]) * kbuf[j * ZK_F + idx];
                ybuf[idx] = v;
                outc[i] = v;
            }
        }
        __syncthreads();
    }
}

// ---------------------------------------------------------------------------
extern "C" void kernel_launch(void *const *d_in, const int *in_sizes, int n_in,
                              void *d_out, int out_size) {
    const float *ts = (const float *)d_in[0];
    const float *y0 = (const float *)d_in[1];
    const float *W0 = (const float *)d_in[2];
    const float *b0 = (const float *)d_in[3];
    const float *W1 = (const float *)d_in[4];
    const float *b1 = (const float *)d_in[5];
    const float *W2 = (const float *)d_in[6];
    const float *b2 = (const float *)d_in[7];
    const float *W3 = (const float *)d_in[8];
    const float *b3 = (const float *)d_in[9];
    float *out = (float *)d_out;

    pack_kernel<<<(BPK_TOTAL + 255) / 256, 256>>>(W0, W1, W2, W3);

    cudaFuncSetAttribute(node_kernel,
                         cudaFuncAttributeMaxDynamicSharedMemorySize, SMEM_BYTES);
    node_kernel<<<NCTA, THREADS, SMEM_BYTES>>>(ts, y0, b0, b1, b2, b3, out);
}